// round 1
// baseline (speedup 1.0000x reference)
#include <cuda_runtime.h>
#include <cuda_bf16.h>
#include <math.h>

// ---------------------------------------------------------------------------
// SpatialModel: 3-layer GATConv (heads=1, self loops w/ mean edge fill) on two
// graphs (N=50000, E=800000), mean pool, MLP head -> [1,3] logits.
//
// Strategy:
//   per graph: build dst-CSR (deg histogram -> single-block scan -> scatter),
//   then per layer: GEMM h=x@W, per-node dots hs/hd, scalar c=We·a_e,
//   warp-per-node segment-softmax aggregation (no float atomics on hot path).
// ---------------------------------------------------------------------------

#define MAX_N 50000
#define MAX_E 800000

// scratch (static device globals -- no allocation allowed)
__device__ float g_h[MAX_N * 128];
__device__ float g_x[MAX_N * 128];
__device__ float g_hs[MAX_N];
__device__ float g_hd[MAX_N];
__device__ int   g_deg[MAX_N];
__device__ float g_loopsum[MAX_N];
__device__ float g_loopattr[MAX_N];
__device__ int   g_offs[MAX_N + 1];
__device__ int   g_cursor[MAX_N];
__device__ int   g_csrsrc[MAX_E];
__device__ float g_csrcol[MAX_E];
__device__ float g_gvec[128];   // pooled means: graph0 [0:64), graph1 [64:128)
__device__ float g_c;           // per-layer scalar We . a_e

// ---------------------------------------------------------------------------
__global__ void zero_int_k(int* p, int n) {
    int i = blockIdx.x * blockDim.x + threadIdx.x;
    if (i < n) p[i] = 0;
}
__global__ void zero_float_k(float* p, int n) {
    int i = blockIdx.x * blockDim.x + threadIdx.x;
    if (i < n) p[i] = 0.f;
}

// histogram of in-degree + sum of edge attr per dst
__global__ void build_deg_k(const int* __restrict__ dst, const float* __restrict__ col,
                            int* deg, float* lsum, int E) {
    int i = blockIdx.x * blockDim.x + threadIdx.x;
    if (i < E) {
        int d = dst[i];
        atomicAdd(&deg[d], 1);
        atomicAdd(&lsum[d], col[i]);
    }
}

// single-block exclusive scan of deg -> offs, also loop_attr and cursor init
__global__ void scan_k(const int* __restrict__ deg, const float* __restrict__ lsum,
                       int* offs, int* cursor, float* lattr, int n) {
    __shared__ int part[1024];
    int t = threadIdx.x;
    int chunk = (n + 1023) / 1024;
    int b = t * chunk;
    int e = min(n, b + chunk);
    int s = 0;
    for (int i = b; i < e; i++) s += deg[i];
    part[t] = s;
    __syncthreads();
    // Hillis-Steele inclusive scan
    for (int d = 1; d < 1024; d <<= 1) {
        int v = (t >= d) ? part[t - d] : 0;
        __syncthreads();
        part[t] += v;
        __syncthreads();
    }
    int run = part[t] - s;  // exclusive prefix
    for (int i = b; i < e; i++) {
        offs[i] = run;
        cursor[i] = run;
        int dg = deg[i];
        run += dg;
        lattr[i] = lsum[i] / (float)max(dg, 1);
    }
    if (t == 1023) offs[n] = run;
}

__global__ void scatter_k(const int* __restrict__ src, const int* __restrict__ dst,
                          const float* __restrict__ col,
                          int* cursor, int* csrc, float* ccol, int E) {
    int i = blockIdx.x * blockDim.x + threadIdx.x;
    if (i < E) {
        int d = dst[i];
        int p = atomicAdd(&cursor[d], 1);
        csrc[p] = src[i];
        ccol[p] = col[i];
    }
}

// ---------------------------------------------------------------------------
// GEMM: C[M,N] = A[M,K] @ B[K,N], fp32, BM=BN=64, BK=16, 4x4 per thread.
__global__ void gemm_k(const float* __restrict__ A, const float* __restrict__ B,
                       float* __restrict__ C, int M, int K, int N) {
    __shared__ float As[16][65];
    __shared__ float Bs[16][65];
    int tid = threadIdx.x;          // 256 threads
    int tx = tid & 15, ty = tid >> 4;
    int rowBase = blockIdx.x * 64, colBase = blockIdx.y * 64;
    float acc[4][4] = {};
    for (int k0 = 0; k0 < K; k0 += 16) {
        for (int i = tid; i < 64 * 16; i += 256) {
            int r = i >> 4, kk = i & 15;
            int gr = rowBase + r, gk = k0 + kk;
            As[kk][r] = (gr < M && gk < K) ? A[(size_t)gr * K + gk] : 0.f;
        }
        for (int i = tid; i < 16 * 64; i += 256) {
            int kk = i >> 6, c = i & 63;
            int gk = k0 + kk, gc = colBase + c;
            Bs[kk][c] = (gk < K && gc < N) ? B[(size_t)gk * N + gc] : 0.f;
        }
        __syncthreads();
        #pragma unroll
        for (int kk = 0; kk < 16; kk++) {
            float a[4], b[4];
            #pragma unroll
            for (int i = 0; i < 4; i++) a[i] = As[kk][ty * 4 + i];
            #pragma unroll
            for (int j = 0; j < 4; j++) b[j] = Bs[kk][tx * 4 + j];
            #pragma unroll
            for (int i = 0; i < 4; i++)
                #pragma unroll
                for (int j = 0; j < 4; j++) acc[i][j] += a[i] * b[j];
        }
        __syncthreads();
    }
    #pragma unroll
    for (int i = 0; i < 4; i++) {
        int gr = rowBase + ty * 4 + i;
        if (gr >= M) continue;
        #pragma unroll
        for (int j = 0; j < 4; j++) {
            int gc = colBase + tx * 4 + j;
            if (gc < N) C[(size_t)gr * N + gc] = acc[i][j];
        }
    }
}

// per-node dots hs = h.a_src, hd = h.a_dst (warp per node)
__global__ void dots_k(const float* __restrict__ h, const float* __restrict__ asrc,
                       const float* __restrict__ adst, float* hs, float* hd,
                       int n, int C) {
    int w = (blockIdx.x * blockDim.x + threadIdx.x) >> 5;
    if (w >= n) return;
    int lane = threadIdx.x & 31;
    float s = 0.f, d = 0.f;
    const float* hr = h + (size_t)w * C;
    for (int k = lane; k < C; k += 32) {
        float v = hr[k];
        s += v * asrc[k];
        d += v * adst[k];
    }
    #pragma unroll
    for (int o = 16; o; o >>= 1) {
        s += __shfl_xor_sync(0xffffffffu, s, o);
        d += __shfl_xor_sync(0xffffffffu, d, o);
    }
    if (lane == 0) { hs[w] = s; hd[w] = d; }
}

// scalar c = sum_k We[0,k] * a_e[k]
__global__ void cscalar_k(const float* __restrict__ We, const float* __restrict__ ae,
                          float* out, int C) {
    __shared__ float s[128];
    int t = threadIdx.x;
    s[t] = (t < C) ? We[t] * ae[t] : 0.f;
    __syncthreads();
    for (int o = 64; o; o >>= 1) {
        if (t < o) s[t] += s[t + o];
        __syncthreads();
    }
    if (t == 0) *out = s[0];
}

__device__ __forceinline__ float leaky02(float a) {
    return a > 0.f ? a : 0.2f * a;
}

// warp-per-node GAT aggregation: segment softmax + weighted sum + bias + elu
template <int C>
__global__ void gat_agg_k(const float* __restrict__ h, const float* __restrict__ hs,
                          const float* __restrict__ hd, const int* __restrict__ offs,
                          const int* __restrict__ csrc, const float* __restrict__ ccol,
                          const float* __restrict__ lattr, const float* __restrict__ bias,
                          const float* __restrict__ cptr, float* __restrict__ xout,
                          int n) {
    int w = (blockIdx.x * blockDim.x + threadIdx.x) >> 5;
    if (w >= n) return;
    int lane = threadIdx.x & 31;
    const int NJ = C / 32;
    float c = *cptr;
    float hdn = hd[w];
    float aself = leaky02(hs[w] + hdn + lattr[w] * c);
    int beg = offs[w], end = offs[w + 1];

    // pass 1: segment max (lane-strided)
    float amax = aself;
    for (int e = beg + lane; e < end; e += 32) {
        float a = leaky02(hs[csrc[e]] + hdn + ccol[e] * c);
        amax = fmaxf(amax, a);
    }
    #pragma unroll
    for (int o = 16; o; o >>= 1) amax = fmaxf(amax, __shfl_xor_sync(0xffffffffu, amax, o));

    // pass 2: exp weights + weighted gather of h[src] rows
    float acc[NJ];
    #pragma unroll
    for (int j = 0; j < NJ; j++) acc[j] = 0.f;
    float denom = 0.f;
    for (int e = beg; e < end; e++) {
        int s = csrc[e];
        float a = leaky02(hs[s] + hdn + ccol[e] * c);
        float ex = __expf(a - amax);
        denom += ex;
        const float* hr = h + (size_t)s * C;
        #pragma unroll
        for (int j = 0; j < NJ; j++) acc[j] += ex * hr[lane + 32 * j];
    }
    // self loop
    {
        float ex = __expf(aself - amax);
        denom += ex;
        const float* hr = h + (size_t)w * C;
        #pragma unroll
        for (int j = 0; j < NJ; j++) acc[j] += ex * hr[lane + 32 * j];
    }
    float inv = 1.f / denom;
    float* xr = xout + (size_t)w * C;
    #pragma unroll
    for (int j = 0; j < NJ; j++) {
        float v = acc[j] * inv + bias[lane + 32 * j];
        v = v > 0.f ? v : expm1f(v);   // elu
        xr[lane + 32 * j] = v;
    }
}

// column sums of x[n,64] into g (g pre-zeroed)
__global__ void colsum_k(const float* __restrict__ x, float* g, int n) {
    int c = threadIdx.x;  // 64 threads
    float s = 0.f;
    for (int r = blockIdx.x; r < n; r += gridDim.x) s += x[(size_t)r * 64 + c];
    atomicAdd(&g[c], s);
}

// head: v_i = [mean_i, xnorm_i] @ W_lin + b_lin ; logits = relu([v1,v2]@Wc1+b)@Wc2+b
__global__ void head_k(const float* __restrict__ g, const float* __restrict__ xn1,
                       const float* __restrict__ xn2, const float* __restrict__ Wlin,
                       const float* __restrict__ blin, const float* __restrict__ Wc1,
                       const float* __restrict__ bc1, const float* __restrict__ Wc2,
                       const float* __restrict__ bc2, float* __restrict__ out, int n) {
    __shared__ float v[128];
    __shared__ float hh[16];
    int t = threadIdx.x;  // 128
    int gi = t >> 6, c = t & 63;
    const float* gg = g + gi * 64;
    const float* xn = gi ? xn2 : xn1;
    float inv = 1.f / (float)n;
    float s = blin[c];
    for (int k = 0; k < 64; k++) s += (gg[k] * inv) * Wlin[k * 64 + c];
    for (int k = 0; k < 16; k++) s += xn[k] * Wlin[(64 + k) * 64 + c];
    v[t] = s;
    __syncthreads();
    if (t < 16) {
        float a = bc1[t];
        for (int k = 0; k < 128; k++) a += v[k] * Wc1[k * 16 + t];
        hh[t] = fmaxf(a, 0.f);
    }
    __syncthreads();
    if (t < 3) {
        float a = bc2[t];
        for (int k = 0; k < 16; k++) a += hh[k] * Wc2[k * 3 + t];
        out[t] = a;
    }
}

// ---------------------------------------------------------------------------
extern "C" void kernel_launch(void* const* d_in, const int* in_sizes, int n_in,
                              void* d_out, int out_size) {
    const int IN = 7;
    const int N = in_sizes[0] / IN;      // 50000
    const int E = in_sizes[2] / 2;       // 800000

    // resolve scratch pointers
    float *p_h, *p_x, *p_hs, *p_hd, *p_lsum, *p_lattr, *p_ccol, *p_g, *p_c;
    int *p_deg, *p_offs, *p_cursor, *p_csrc;
    cudaGetSymbolAddress((void**)&p_h, g_h);
    cudaGetSymbolAddress((void**)&p_x, g_x);
    cudaGetSymbolAddress((void**)&p_hs, g_hs);
    cudaGetSymbolAddress((void**)&p_hd, g_hd);
    cudaGetSymbolAddress((void**)&p_lsum, g_loopsum);
    cudaGetSymbolAddress((void**)&p_lattr, g_loopattr);
    cudaGetSymbolAddress((void**)&p_ccol, g_csrcol);
    cudaGetSymbolAddress((void**)&p_g, g_gvec);
    cudaGetSymbolAddress((void**)&p_c, g_c);
    cudaGetSymbolAddress((void**)&p_deg, g_deg);
    cudaGetSymbolAddress((void**)&p_offs, g_offs);
    cudaGetSymbolAddress((void**)&p_cursor, g_cursor);
    cudaGetSymbolAddress((void**)&p_csrc, g_csrsrc);

    const float* x_in[2]    = {(const float*)d_in[0], (const float*)d_in[1]};
    const int*   ei[2]      = {(const int*)d_in[2], (const int*)d_in[3]};
    const float* xnorm[2]   = {(const float*)d_in[4], (const float*)d_in[5]};
    const float* ecol[2]    = {(const float*)d_in[6], (const float*)d_in[7]};

    // layer params: base index 8 + 6*layer: W, a_src, a_dst, We, a_e, b
    const float* W[3]; const float* asrc[3]; const float* adst[3];
    const float* We[3]; const float* ae[3]; const float* bb[3];
    for (int l = 0; l < 3; l++) {
        W[l]    = (const float*)d_in[8 + 6 * l + 0];
        asrc[l] = (const float*)d_in[8 + 6 * l + 1];
        adst[l] = (const float*)d_in[8 + 6 * l + 2];
        We[l]   = (const float*)d_in[8 + 6 * l + 3];
        ae[l]   = (const float*)d_in[8 + 6 * l + 4];
        bb[l]   = (const float*)d_in[8 + 6 * l + 5];
    }
    const float* Wlin = (const float*)d_in[26];
    const float* blin = (const float*)d_in[27];
    const float* Wc1  = (const float*)d_in[28];
    const float* bc1  = (const float*)d_in[29];
    const float* Wc2  = (const float*)d_in[30];
    const float* bc2  = (const float*)d_in[31];

    const int Cdim[3] = {128, 128, 64};
    const int Kdim[3] = {IN, 128, 128};

    const int eBlocks = (E + 255) / 256;
    const int nBlocks = (N + 255) / 256;
    const int warpBlocks = (N * 32 + 255) / 256;

    zero_float_k<<<1, 128>>>(p_g, 128);

    for (int gph = 0; gph < 2; gph++) {
        const int* src = ei[gph];
        const int* dst = ei[gph] + E;
        const float* col = ecol[gph];

        // build CSR by destination
        zero_int_k<<<nBlocks, 256>>>(p_deg, N);
        zero_float_k<<<nBlocks, 256>>>(p_lsum, N);
        build_deg_k<<<eBlocks, 256>>>(dst, col, p_deg, p_lsum, E);
        scan_k<<<1, 1024>>>(p_deg, p_lsum, p_offs, p_cursor, p_lattr, N);
        scatter_k<<<eBlocks, 256>>>(src, dst, col, p_cursor, p_csrc, p_ccol, E);

        for (int l = 0; l < 3; l++) {
            const float* xin = (l == 0) ? x_in[gph] : p_x;
            int K = Kdim[l], C = Cdim[l];
            dim3 ggrid((N + 63) / 64, (C + 63) / 64);
            gemm_k<<<ggrid, 256>>>(xin, W[l], p_h, N, K, C);
            dots_k<<<warpBlocks, 256>>>(p_h, asrc[l], adst[l], p_hs, p_hd, N, C);
            cscalar_k<<<1, 128>>>(We[l], ae[l], p_c, C);
            if (C == 128)
                gat_agg_k<128><<<warpBlocks, 256>>>(p_h, p_hs, p_hd, p_offs, p_csrc,
                                                    p_ccol, p_lattr, bb[l], p_c, p_x, N);
            else
                gat_agg_k<64><<<warpBlocks, 256>>>(p_h, p_hs, p_hd, p_offs, p_csrc,
                                                   p_ccol, p_lattr, bb[l], p_c, p_x, N);
        }
        colsum_k<<<512, 64>>>(p_x, p_g + gph * 64, N);
    }

    head_k<<<1, 128>>>(p_g, xnorm[0], xnorm[1], Wlin, blin, Wc1, bc1, Wc2, bc2,
                       (float*)d_out, N);
}

// round 2
// speedup vs baseline: 1.6870x; 1.6870x over previous
#include <cuda_runtime.h>
#include <cuda_bf16.h>
#include <math.h>

// ---------------------------------------------------------------------------
// SpatialModel: 3-layer GATConv on two graphs (N=50000, E=800000), mean pool,
// MLP head -> [1,3] logits.
//
// R2: (1) 128x64 tile fp32 GEMM (FFMA-bound, float4 smem), (2) the two
// independent graphs run on forked streams (overlap FMA-bound GEMM with
// L2-bound aggregation / CSR build), (3) multi-block scan, vectorized gathers.
// ---------------------------------------------------------------------------

#define MAX_N 50000
#define MAX_E 800000
#define TILE 512

// per-graph scratch (index 0/1 = graph id). No allocation allowed -> statics.
__device__ float g_h[2][MAX_N * 128];
__device__ float g_x[2][MAX_N * 128];
__device__ float g_hs[2][MAX_N];
__device__ float g_hd[2][MAX_N];
__device__ int   g_deg[2][MAX_N];
__device__ float g_loopsum[2][MAX_N];
__device__ float g_loopattr[2][MAX_N];
__device__ int   g_offs[2][MAX_N + 1];
__device__ int   g_cursor[2][MAX_N];
__device__ int   g_csrsrc[2][MAX_E];
__device__ float g_csrcol[2][MAX_E];
__device__ int   g_tsum[2][128];
__device__ float g_c[2];
__device__ float g_gvec[128];   // pooled sums: graph0 [0:64), graph1 [64:128)

// ---------------------------------------------------------------------------
__global__ void zero_int_k(int* p, int n) {
    int i = blockIdx.x * blockDim.x + threadIdx.x;
    if (i < n) p[i] = 0;
}
__global__ void zero_float_k(float* p, int n) {
    int i = blockIdx.x * blockDim.x + threadIdx.x;
    if (i < n) p[i] = 0.f;
}

__global__ void build_deg_k(const int* __restrict__ dst, const float* __restrict__ col,
                            int* deg, float* lsum, int E) {
    int i = blockIdx.x * blockDim.x + threadIdx.x;
    if (i < E) {
        int d = dst[i];
        atomicAdd(&deg[d], 1);
        atomicAdd(&lsum[d], col[i]);
    }
}

// 3-phase exclusive scan of deg -> offs (+ cursor init + loop_attr)
__global__ void scan1_k(const int* __restrict__ deg, int* tsum, int n) {
    __shared__ int sh[256];
    int b = blockIdx.x, t = threadIdx.x;
    int i0 = b * TILE;
    int s = 0;
    int i = i0 + t;        if (i < n) s += deg[i];
    i = i0 + 256 + t;      if (i < n) s += deg[i];
    sh[t] = s;
    __syncthreads();
    for (int o = 128; o; o >>= 1) { if (t < o) sh[t] += sh[t + o]; __syncthreads(); }
    if (t == 0) tsum[b] = sh[0];
}
__global__ void scan2_k(int* tsum, int nT) {
    __shared__ int sh[128];
    int t = threadIdx.x;
    int v0 = (t < nT) ? tsum[t] : 0;
    sh[t] = v0;
    __syncthreads();
    for (int d = 1; d < 128; d <<= 1) {
        int v = (t >= d) ? sh[t - d] : 0;
        __syncthreads();
        sh[t] += v;
        __syncthreads();
    }
    if (t < nT) tsum[t] = sh[t] - v0;   // exclusive
}
__global__ void scan3_k(const int* __restrict__ deg, const int* __restrict__ tsum,
                        const float* __restrict__ lsum, int* offs, int* cursor,
                        float* lattr, int n) {
    __shared__ int sh[TILE];
    int b = blockIdx.x, t = threadIdx.x;
    int i = b * TILE + t;
    int d = (i < n) ? deg[i] : 0;
    sh[t] = d;
    __syncthreads();
    for (int o = 1; o < TILE; o <<= 1) {
        int v = (t >= o) ? sh[t - o] : 0;
        __syncthreads();
        sh[t] += v;
        __syncthreads();
    }
    if (i < n) {
        int base = tsum[b];
        int off = base + sh[t] - d;
        offs[i] = off;
        cursor[i] = off;
        lattr[i] = lsum[i] / (float)max(d, 1);
        if (i == n - 1) offs[n] = base + sh[t];
    }
}

__global__ void scatter_k(const int* __restrict__ src, const int* __restrict__ dst,
                          const float* __restrict__ col,
                          int* cursor, int* csrc, float* ccol, int E) {
    int i = blockIdx.x * blockDim.x + threadIdx.x;
    if (i < E) {
        int d = dst[i];
        int p = atomicAdd(&cursor[d], 1);
        csrc[p] = src[i];
        ccol[p] = col[i];
    }
}

// ---------------------------------------------------------------------------
// GEMM: C[M,N] = A[M,K] @ B[K,N], fp32. BM=128, BN=64, BK=16, 256 thr, 8x4/thr.
template <bool VEC>
__global__ void __launch_bounds__(256)
gemm_k(const float* __restrict__ A, const float* __restrict__ B,
       float* __restrict__ C, int M, int K, int N) {
    __shared__ float As[16][132];   // pad: 132*4B=528B row, 16B aligned
    __shared__ float Bs[16][64];
    int tid = threadIdx.x;
    int tx = tid & 15, ty = tid >> 4;
    int rowBase = blockIdx.x * 128, colBase = blockIdx.y * 64;
    float acc[8][4] = {};

    for (int k0 = 0; k0 < K; k0 += 16) {
        if (VEC) {
            #pragma unroll
            for (int q = 0; q < 2; q++) {
                int f = q * 256 + tid;      // 512 float4 total
                int r = f >> 2, c4 = f & 3;
                int gr = rowBase + r;
                float4 v = make_float4(0.f, 0.f, 0.f, 0.f);
                if (gr < M) v = *(const float4*)(A + (size_t)gr * K + k0 + c4 * 4);
                As[c4 * 4 + 0][r] = v.x;
                As[c4 * 4 + 1][r] = v.y;
                As[c4 * 4 + 2][r] = v.z;
                As[c4 * 4 + 3][r] = v.w;
            }
            {
                int kk = tid >> 4, c4 = tid & 15;
                float4 v = *(const float4*)(B + (size_t)(k0 + kk) * N + colBase + c4 * 4);
                *(float4*)&Bs[kk][c4 * 4] = v;
            }
        } else {
            for (int i = tid; i < 128 * 16; i += 256) {
                int r = i >> 4, kk = i & 15;
                int gr = rowBase + r, gk = k0 + kk;
                As[kk][r] = (gr < M && gk < K) ? A[(size_t)gr * K + gk] : 0.f;
            }
            for (int i = tid; i < 16 * 64; i += 256) {
                int kk = i >> 6, cc = i & 63;
                int gk = k0 + kk;
                Bs[kk][cc] = (gk < K) ? B[(size_t)gk * N + colBase + cc] : 0.f;
            }
        }
        __syncthreads();
        #pragma unroll
        for (int kk = 0; kk < 16; kk++) {
            float a[8], b[4];
            *(float4*)&a[0] = *(const float4*)&As[kk][ty * 8];
            *(float4*)&a[4] = *(const float4*)&As[kk][ty * 8 + 4];
            *(float4*)&b[0] = *(const float4*)&Bs[kk][tx * 4];
            #pragma unroll
            for (int i = 0; i < 8; i++)
                #pragma unroll
                for (int j = 0; j < 4; j++) acc[i][j] += a[i] * b[j];
        }
        __syncthreads();
    }
    #pragma unroll
    for (int i = 0; i < 8; i++) {
        int gr = rowBase + ty * 8 + i;
        if (gr < M) {
            float4 v = make_float4(acc[i][0], acc[i][1], acc[i][2], acc[i][3]);
            *(float4*)(C + (size_t)gr * N + colBase + tx * 4) = v;
        }
    }
}

// per-node dots hs = h.a_src, hd = h.a_dst (warp per node)
__global__ void dots_k(const float* __restrict__ h, const float* __restrict__ asrc,
                       const float* __restrict__ adst, float* hs, float* hd,
                       int n, int C) {
    int w = (blockIdx.x * blockDim.x + threadIdx.x) >> 5;
    if (w >= n) return;
    int lane = threadIdx.x & 31;
    float s = 0.f, d = 0.f;
    const float* hr = h + (size_t)w * C;
    for (int k = lane; k < C; k += 32) {
        float v = hr[k];
        s += v * asrc[k];
        d += v * adst[k];
    }
    #pragma unroll
    for (int o = 16; o; o >>= 1) {
        s += __shfl_xor_sync(0xffffffffu, s, o);
        d += __shfl_xor_sync(0xffffffffu, d, o);
    }
    if (lane == 0) { hs[w] = s; hd[w] = d; }
}

__global__ void cscalar_k(const float* __restrict__ We, const float* __restrict__ ae,
                          float* out, int C) {
    __shared__ float s[128];
    int t = threadIdx.x;
    s[t] = (t < C) ? We[t] * ae[t] : 0.f;
    __syncthreads();
    for (int o = 64; o; o >>= 1) {
        if (t < o) s[t] += s[t + o];
        __syncthreads();
    }
    if (t == 0) *out = s[0];
}

__device__ __forceinline__ float leaky02(float a) {
    return a > 0.f ? a : 0.2f * a;
}

// warp-per-node GAT aggregation: segment softmax + weighted gather + bias + elu
template <int C>
__global__ void gat_agg_k(const float* __restrict__ h, const float* __restrict__ hs,
                          const float* __restrict__ hd, const int* __restrict__ offs,
                          const int* __restrict__ csrc, const float* __restrict__ ccol,
                          const float* __restrict__ lattr, const float* __restrict__ bias,
                          const float* __restrict__ cptr, float* __restrict__ xout,
                          int n) {
    constexpr int VL = C / 32;   // 4 (C=128) or 2 (C=64)
    int w = (blockIdx.x * blockDim.x + threadIdx.x) >> 5;
    if (w >= n) return;
    int lane = threadIdx.x & 31;
    float c = *cptr;
    float hdn = hd[w];
    float aself = leaky02(hs[w] + hdn + lattr[w] * c);
    int beg = offs[w], end = offs[w + 1];

    // pass 1: segment max
    float amax = aself;
    for (int e = beg + lane; e < end; e += 32)
        amax = fmaxf(amax, leaky02(hs[csrc[e]] + hdn + ccol[e] * c));
    #pragma unroll
    for (int o = 16; o; o >>= 1) amax = fmaxf(amax, __shfl_xor_sync(0xffffffffu, amax, o));

    // pass 2: exp weights + vectorized weighted gather of h[src] rows
    float acc[VL];
    #pragma unroll
    for (int j = 0; j < VL; j++) acc[j] = 0.f;
    float denom = 0.f;
    for (int e = beg; e < end; e++) {
        int s = csrc[e];
        float ex = __expf(leaky02(hs[s] + hdn + ccol[e] * c) - amax);
        denom += ex;
        const float* hr = h + (size_t)s * C + lane * VL;
        if (VL == 4) {
            float4 v = *(const float4*)hr;
            acc[0] += ex * v.x; acc[1] += ex * v.y;
            acc[2] += ex * v.z; acc[3] += ex * v.w;
        } else {
            float2 v = *(const float2*)hr;
            acc[0] += ex * v.x; acc[1] += ex * v.y;
        }
    }
    {   // self loop
        float ex = __expf(aself - amax);
        denom += ex;
        const float* hr = h + (size_t)w * C + lane * VL;
        if (VL == 4) {
            float4 v = *(const float4*)hr;
            acc[0] += ex * v.x; acc[1] += ex * v.y;
            acc[2] += ex * v.z; acc[3] += ex * v.w;
        } else {
            float2 v = *(const float2*)hr;
            acc[0] += ex * v.x; acc[1] += ex * v.y;
        }
    }
    float inv = 1.f / denom;
    float out[VL];
    #pragma unroll
    for (int j = 0; j < VL; j++) {
        float v = acc[j] * inv + bias[lane * VL + j];
        out[j] = v > 0.f ? v : expm1f(v);   // elu
    }
    float* xr = xout + (size_t)w * C + lane * VL;
    if (VL == 4) *(float4*)xr = make_float4(out[0], out[1], out[2], out[3]);
    else         *(float2*)xr = make_float2(out[0], out[1]);
}

// column sums of x[n,64] into g (g pre-zeroed)
__global__ void colsum_k(const float* __restrict__ x, float* g, int n) {
    int c = threadIdx.x;  // 64 threads
    float s = 0.f;
    for (int r = blockIdx.x; r < n; r += gridDim.x) s += x[(size_t)r * 64 + c];
    atomicAdd(&g[c], s);
}

__global__ void head_k(const float* __restrict__ g, const float* __restrict__ xn1,
                       const float* __restrict__ xn2, const float* __restrict__ Wlin,
                       const float* __restrict__ blin, const float* __restrict__ Wc1,
                       const float* __restrict__ bc1, const float* __restrict__ Wc2,
                       const float* __restrict__ bc2, float* __restrict__ out, int n) {
    __shared__ float v[128];
    __shared__ float hh[16];
    int t = threadIdx.x;  // 128
    int gi = t >> 6, c = t & 63;
    const float* gg = g + gi * 64;
    const float* xn = gi ? xn2 : xn1;
    float inv = 1.f / (float)n;
    float s = blin[c];
    for (int k = 0; k < 64; k++) s += (gg[k] * inv) * Wlin[k * 64 + c];
    for (int k = 0; k < 16; k++) s += xn[k] * Wlin[(64 + k) * 64 + c];
    v[t] = s;
    __syncthreads();
    if (t < 16) {
        float a = bc1[t];
        for (int k = 0; k < 128; k++) a += v[k] * Wc1[k * 16 + t];
        hh[t] = fmaxf(a, 0.f);
    }
    __syncthreads();
    if (t < 3) {
        float a = bc2[t];
        for (int k = 0; k < 16; k++) a += hh[k] * Wc2[k * 3 + t];
        out[t] = a;
    }
}

// ---------------------------------------------------------------------------
extern "C" void kernel_launch(void* const* d_in, const int* in_sizes, int n_in,
                              void* d_out, int out_size) {
    const int IN = 7;
    const int N = in_sizes[0] / IN;      // 50000
    const int E = in_sizes[2] / 2;       // 800000

    // one-time stream/event creation (host resources, not device memory)
    static cudaStream_t s2 = nullptr;
    static cudaEvent_t evF = nullptr, evJ = nullptr;
    if (!s2) {
        cudaStreamCreateWithFlags(&s2, cudaStreamNonBlocking);
        cudaEventCreateWithFlags(&evF, cudaEventDisableTiming);
        cudaEventCreateWithFlags(&evJ, cudaEventDisableTiming);
    }

    // resolve scratch base pointers
    float *b_h, *b_x, *b_hs, *b_hd, *b_lsum, *b_lattr, *b_ccol, *p_g, *b_c;
    int *b_deg, *b_offs, *b_cursor, *b_csrc, *b_tsum;
    cudaGetSymbolAddress((void**)&b_h, g_h);
    cudaGetSymbolAddress((void**)&b_x, g_x);
    cudaGetSymbolAddress((void**)&b_hs, g_hs);
    cudaGetSymbolAddress((void**)&b_hd, g_hd);
    cudaGetSymbolAddress((void**)&b_lsum, g_loopsum);
    cudaGetSymbolAddress((void**)&b_lattr, g_loopattr);
    cudaGetSymbolAddress((void**)&b_ccol, g_csrcol);
    cudaGetSymbolAddress((void**)&p_g, g_gvec);
    cudaGetSymbolAddress((void**)&b_c, g_c);
    cudaGetSymbolAddress((void**)&b_deg, g_deg);
    cudaGetSymbolAddress((void**)&b_offs, g_offs);
    cudaGetSymbolAddress((void**)&b_cursor, g_cursor);
    cudaGetSymbolAddress((void**)&b_csrc, g_csrsrc);
    cudaGetSymbolAddress((void**)&b_tsum, g_tsum);

    const float* x_in[2]  = {(const float*)d_in[0], (const float*)d_in[1]};
    const int*   ei[2]    = {(const int*)d_in[2], (const int*)d_in[3]};
    const float* xnorm[2] = {(const float*)d_in[4], (const float*)d_in[5]};
    const float* ecol[2]  = {(const float*)d_in[6], (const float*)d_in[7]};

    const float* W[3]; const float* asrc[3]; const float* adst[3];
    const float* We[3]; const float* ae[3]; const float* bb[3];
    for (int l = 0; l < 3; l++) {
        W[l]    = (const float*)d_in[8 + 6 * l + 0];
        asrc[l] = (const float*)d_in[8 + 6 * l + 1];
        adst[l] = (const float*)d_in[8 + 6 * l + 2];
        We[l]   = (const float*)d_in[8 + 6 * l + 3];
        ae[l]   = (const float*)d_in[8 + 6 * l + 4];
        bb[l]   = (const float*)d_in[8 + 6 * l + 5];
    }
    const float* Wlin = (const float*)d_in[26];
    const float* blin = (const float*)d_in[27];
    const float* Wc1  = (const float*)d_in[28];
    const float* bc1  = (const float*)d_in[29];
    const float* Wc2  = (const float*)d_in[30];
    const float* bc2  = (const float*)d_in[31];

    const int Cdim[3] = {128, 128, 64};
    const int Kdim[3] = {IN, 128, 128};

    const int eBlocks = (E + 255) / 256;
    const int nBlocks = (N + 255) / 256;
    const int warpBlocks = (N * 32 + 255) / 256;
    const int nT = (N + TILE - 1) / TILE;

    // zero pooled vector, then fork graph-1 pipeline onto s2
    zero_float_k<<<1, 128, 0, 0>>>(p_g, 128);
    cudaEventRecord(evF, 0);
    cudaStreamWaitEvent(s2, evF, 0);

    for (int gph = 0; gph < 2; gph++) {
        cudaStream_t st = gph ? s2 : (cudaStream_t)0;
        const int* src = ei[gph];
        const int* dst = ei[gph] + E;
        const float* col = ecol[gph];

        float* p_h = b_h + (size_t)gph * MAX_N * 128;
        float* p_x = b_x + (size_t)gph * MAX_N * 128;
        float* p_hs = b_hs + gph * MAX_N;
        float* p_hd = b_hd + gph * MAX_N;
        float* p_lsum = b_lsum + gph * MAX_N;
        float* p_lattr = b_lattr + gph * MAX_N;
        float* p_ccol = b_ccol + (size_t)gph * MAX_E;
        float* p_c = b_c + gph;
        int* p_deg = b_deg + gph * MAX_N;
        int* p_offs = b_offs + gph * (MAX_N + 1);
        int* p_cursor = b_cursor + gph * MAX_N;
        int* p_csrc = b_csrc + (size_t)gph * MAX_E;
        int* p_tsum = b_tsum + gph * 128;

        // build CSR by destination
        zero_int_k<<<nBlocks, 256, 0, st>>>(p_deg, N);
        zero_float_k<<<nBlocks, 256, 0, st>>>(p_lsum, N);
        build_deg_k<<<eBlocks, 256, 0, st>>>(dst, col, p_deg, p_lsum, E);
        scan1_k<<<nT, 256, 0, st>>>(p_deg, p_tsum, N);
        scan2_k<<<1, 128, 0, st>>>(p_tsum, nT);
        scan3_k<<<nT, TILE, 0, st>>>(p_deg, p_tsum, p_lsum, p_offs, p_cursor, p_lattr, N);
        scatter_k<<<eBlocks, 256, 0, st>>>(src, dst, col, p_cursor, p_csrc, p_ccol, E);

        for (int l = 0; l < 3; l++) {
            const float* xin = (l == 0) ? x_in[gph] : p_x;
            int K = Kdim[l], C = Cdim[l];
            dim3 ggrid((N + 127) / 128, C / 64);
            if (K % 16 == 0)
                gemm_k<true><<<ggrid, 256, 0, st>>>(xin, W[l], p_h, N, K, C);
            else
                gemm_k<false><<<ggrid, 256, 0, st>>>(xin, W[l], p_h, N, K, C);
            dots_k<<<warpBlocks, 256, 0, st>>>(p_h, asrc[l], adst[l], p_hs, p_hd, N, C);
            cscalar_k<<<1, 128, 0, st>>>(We[l], ae[l], p_c, C);
            if (C == 128)
                gat_agg_k<128><<<warpBlocks, 256, 0, st>>>(p_h, p_hs, p_hd, p_offs,
                                                           p_csrc, p_ccol, p_lattr,
                                                           bb[l], p_c, p_x, N);
            else
                gat_agg_k<64><<<warpBlocks, 256, 0, st>>>(p_h, p_hs, p_hd, p_offs,
                                                          p_csrc, p_ccol, p_lattr,
                                                          bb[l], p_c, p_x, N);
        }
        colsum_k<<<512, 64, 0, st>>>(p_x, p_g + gph * 64, N);
    }

    // join graph-1 stream back into stream 0, then head
    cudaEventRecord(evJ, s2);
    cudaStreamWaitEvent((cudaStream_t)0, evJ, 0);
    head_k<<<1, 128, 0, 0>>>(p_g, xnorm[0], xnorm[1], Wlin, blin, Wc1, bc1, Wc2, bc2,
                             (float*)d_out, N);
}